// round 15
// baseline (speedup 1.0000x reference)
#include <cuda_runtime.h>
#include <cuda_fp16.h>
#include <math.h>

#define NN 50000
#define EE 1600000
#define DIM 128
#define HEADS 4
#define ODIM 32
#define ALPHA 0.2f
#define WPB 8
#define STRIDE 80   // fixed bucket capacity per node (Poisson(32) max ~58)

// ---------------- device scratch ----------------
__device__ __align__(16) __half g_Xh[NN * DIM];   // fp16 copy of X
__device__ __align__(16) __half g_Hh[NN * DIM];   // fp16 features
__device__ __align__(16) float  g_Hs[NN * HEADS];
__device__ __align__(16) float  g_Ht[NN * HEADS];
__device__ int g_cur[NN];                 // per-node edge count (zero at load; re-zeroed by agg)
__device__ int g_csr[NN * STRIDE];        // bucketed tgt lists
__device__ unsigned g_maxh[8];

__device__ __forceinline__ unsigned enc_f(float f) {
    unsigned u = __float_as_uint(f);
    return (u & 0x80000000u) ? ~u : (u | 0x80000000u);
}
__device__ __forceinline__ float dec_f(unsigned u) {
    return (u & 0x80000000u) ? __uint_as_float(u ^ 0x80000000u)
                             : __uint_as_float(~u);
}
__device__ __forceinline__ float lrelu(float x) { return x > 0.f ? x : ALPHA * x; }

__device__ __forceinline__ void mma_f16(float* c, const unsigned* a,
                                        unsigned b0, unsigned b1) {
    asm volatile(
        "mma.sync.aligned.m16n8k16.row.col.f32.f16.f16.f32 "
        "{%0,%1,%2,%3}, {%4,%5,%6,%7}, {%8,%9}, {%0,%1,%2,%3};\n"
        : "+f"(c[0]), "+f"(c[1]), "+f"(c[2]), "+f"(c[3])
        : "r"(a[0]), "r"(a[1]), "r"(a[2]), "r"(a[3]), "r"(b0), "r"(b1));
}

// ---------------- chain A, K0: X -> fp16 ----------------
__global__ void xcvt_kernel(const float* __restrict__ X) {
    int i = blockIdx.x * blockDim.x + threadIdx.x;
    if (i < NN * DIM / 8) {
        const float4* p = (const float4*)X + (size_t)i * 2;
        float4 v0 = p[0], v1 = p[1];
        __half2 h[4];
        h[0] = __floats2half2_rn(v0.x, v0.y);
        h[1] = __floats2half2_rn(v0.z, v0.w);
        h[2] = __floats2half2_rn(v1.x, v1.y);
        h[3] = __floats2half2_rn(v1.z, v1.w);
        *(uint4*)(g_Xh + (size_t)i * 8) = *(uint4*)h;
    }
}

// ---------------- chain A, K1: fp16 HMMA GEMM + fused scores/maxes (R12) ----------------
__global__ __launch_bounds__(256) void gemm_f16(const float* __restrict__ W,
                                                const float* __restrict__ Al,
                                                const float* __restrict__ Ar) {
    if (blockIdx.x == 0 && threadIdx.x < 8) g_maxh[threadIdx.x] = 0u;
    __shared__ __align__(16) __half Xs[128][72];
    __shared__ __align__(16) __half Wt[128][72];   // W transposed: [n][k]
    __shared__ unsigned sm8[8];
    const int tid  = threadIdx.x;
    const int lane = tid & 31;
    const int warp = tid >> 5;
    const int wr = warp >> 1;
    const int wc = warp & 1;
    const int g   = lane >> 2;
    const int tig = lane & 3;
    const int m0 = blockIdx.x * 128;
    if (tid < 8) sm8[tid] = 0u;

    float c[2][8][4];
#pragma unroll
    for (int mi = 0; mi < 2; mi++)
#pragma unroll
        for (int ni = 0; ni < 8; ni++)
#pragma unroll
            for (int j = 0; j < 4; j++) c[mi][ni][j] = 0.f;

    for (int kc = 0; kc < DIM; kc += 64) {
        __syncthreads();
        for (int idx = tid; idx < 128 * 8; idx += 256) {
            int row = idx >> 3;
            int c8  = (idx & 7) * 8;
            int gm = m0 + row;
            uint4 v = make_uint4(0u, 0u, 0u, 0u);
            if (gm < NN) v = *(const uint4*)(g_Xh + (size_t)gm * DIM + kc + c8);
            *(uint4*)&Xs[row][c8] = v;
        }
        for (int idx = tid; idx < 64 * 32; idx += 256) {
            int k  = idx >> 5;
            int n4 = (idx & 31) * 4;
            float4 w = *(const float4*)(W + (size_t)(kc + k) * DIM + n4);
            Wt[n4 + 0][k] = __float2half(w.x);
            Wt[n4 + 1][k] = __float2half(w.y);
            Wt[n4 + 2][k] = __float2half(w.z);
            Wt[n4 + 3][k] = __float2half(w.w);
        }
        __syncthreads();

#pragma unroll
        for (int ks = 0; ks < 4; ks++) {
            const int k0 = ks * 16;
            unsigned a[2][4];
#pragma unroll
            for (int mi = 0; mi < 2; mi++) {
                int r = wr * 32 + mi * 16;
                a[mi][0] = *(const unsigned*)&Xs[r + g][k0 + tig * 2];
                a[mi][1] = *(const unsigned*)&Xs[r + g + 8][k0 + tig * 2];
                a[mi][2] = *(const unsigned*)&Xs[r + g][k0 + tig * 2 + 8];
                a[mi][3] = *(const unsigned*)&Xs[r + g + 8][k0 + tig * 2 + 8];
            }
#pragma unroll
            for (int ni = 0; ni < 8; ni++) {
                int n = wc * 64 + ni * 8 + g;
                unsigned b0 = *(const unsigned*)&Wt[n][k0 + tig * 2];
                unsigned b1 = *(const unsigned*)&Wt[n][k0 + tig * 2 + 8];
                mma_f16(c[0][ni], a[0], b0, b1);
                mma_f16(c[1][ni], a[1], b0, b1);
            }
        }
    }

    const int head0 = wc * 2, head1 = wc * 2 + 1;
    float alv0[8], arv0[8], alv1[8], arv1[8];
#pragma unroll
    for (int ni = 0; ni < 4; ni++)
#pragma unroll
        for (int j = 0; j < 2; j++) {
            int o = ni * 8 + tig * 2 + j;
            alv0[ni * 2 + j] = Al[head0 * ODIM + o];
            arv0[ni * 2 + j] = Ar[head0 * ODIM + o];
            alv1[ni * 2 + j] = Al[head1 * ODIM + o];
            arv1[ni * 2 + j] = Ar[head1 * ODIM + o];
        }
    float mx_s0 = -1e30f, mx_t0 = -1e30f, mx_s1 = -1e30f, mx_t1 = -1e30f;
#pragma unroll
    for (int mi = 0; mi < 2; mi++)
#pragma unroll
        for (int half = 0; half < 2; half++) {
            int row = m0 + wr * 32 + mi * 16 + g + 8 * half;
            float s0 = 0.f, t0 = 0.f, s1 = 0.f, t1 = 0.f;
            if (row < NN) {
#pragma unroll
                for (int ni = 0; ni < 8; ni++) {
                    float v0 = c[mi][ni][half * 2];
                    float v1 = c[mi][ni][half * 2 + 1];
                    *(__half2*)(g_Hh + (size_t)row * DIM + wc * 64 + ni * 8 + tig * 2) =
                        __floats2half2_rn(v0, v1);
                    if (ni < 4) {
                        s0 = fmaf(v0, alv0[ni * 2], s0);
                        s0 = fmaf(v1, alv0[ni * 2 + 1], s0);
                        t0 = fmaf(v0, arv0[ni * 2], t0);
                        t0 = fmaf(v1, arv0[ni * 2 + 1], t0);
                    } else {
                        s1 = fmaf(v0, alv1[(ni - 4) * 2], s1);
                        s1 = fmaf(v1, alv1[(ni - 4) * 2 + 1], s1);
                        t1 = fmaf(v0, arv1[(ni - 4) * 2], t1);
                        t1 = fmaf(v1, arv1[(ni - 4) * 2 + 1], t1);
                    }
                }
            }
            s0 += __shfl_xor_sync(0xffffffffu, s0, 1);
            t0 += __shfl_xor_sync(0xffffffffu, t0, 1);
            s1 += __shfl_xor_sync(0xffffffffu, s1, 1);
            t1 += __shfl_xor_sync(0xffffffffu, t1, 1);
            s0 += __shfl_xor_sync(0xffffffffu, s0, 2);
            t0 += __shfl_xor_sync(0xffffffffu, t0, 2);
            s1 += __shfl_xor_sync(0xffffffffu, s1, 2);
            t1 += __shfl_xor_sync(0xffffffffu, t1, 2);
            if (tig == 0 && row < NN) {
                g_Hs[(size_t)row * 4 + head0] = s0;
                g_Ht[(size_t)row * 4 + head0] = t0;
                g_Hs[(size_t)row * 4 + head1] = s1;
                g_Ht[(size_t)row * 4 + head1] = t1;
                mx_s0 = fmaxf(mx_s0, s0);
                mx_t0 = fmaxf(mx_t0, t0);
                mx_s1 = fmaxf(mx_s1, s1);
                mx_t1 = fmaxf(mx_t1, t1);
            }
        }
    if (tig == 0) {
        atomicMax(&sm8[head0],     enc_f(mx_s0));
        atomicMax(&sm8[4 + head0], enc_f(mx_t0));
        atomicMax(&sm8[head1],     enc_f(mx_s1));
        atomicMax(&sm8[4 + head1], enc_f(mx_t1));
    }
    __syncthreads();
    if (tid < 8) atomicMax(&g_maxh[tid], sm8[tid]);
}

// ---------------- chain B: single-pass bucket scatter ----------------
__global__ void scatter_kernel(const int* __restrict__ ei) {
    int e = blockIdx.x * blockDim.x + threadIdx.x;
    if (e < EE) {
        int src = ei[e];
        int tgt = ei[EE + e];
        int p = atomicAdd(&g_cur[src], 1);
        if (p < STRIDE) g_csr[src * STRIDE + p] = tgt;   // clamp for memory safety
    }
}

// ---------------- join, K6: fused softmax + aggregation + ELU ----------------
__device__ __forceinline__ void agg_step(int j, int lane, int h,
                                         const int* s_tgt, const float* s_e,
                                         float4& acc) {
    int t = s_tgt[j];
    float ej = s_e[j * 4 + h];
    const __half2* hp = (const __half2*)(g_Hh + (size_t)t * DIM + lane * 4);
    __half2 a = hp[0], b = hp[1];
    float2 fa = __half22float2(a);
    float2 fb = __half22float2(b);
    acc.x = fmaf(ej, fa.x, acc.x);
    acc.y = fmaf(ej, fa.y, acc.y);
    acc.z = fmaf(ej, fb.x, acc.z);
    acc.w = fmaf(ej, fb.y, acc.w);
}

__global__ __launch_bounds__(WPB * 32) void agg_kernel(float* __restrict__ out) {
    __shared__ int   s_tgt[WPB][32];
    __shared__ float s_e[WPB][32 * 4];
    int wid  = threadIdx.x >> 5;
    int lane = threadIdx.x & 31;
    int node = blockIdx.x * WPB + wid;
    if (node >= NN) return;
    int h = lane >> 3;
    int deg = min(g_cur[node], STRIDE);
    int start = node * STRIDE;
    int end   = start + deg;
    float4 M4;
    M4.x = lrelu(dec_f(g_maxh[0]) + dec_f(g_maxh[4]));
    M4.y = lrelu(dec_f(g_maxh[1]) + dec_f(g_maxh[5]));
    M4.z = lrelu(dec_f(g_maxh[2]) + dec_f(g_maxh[6]));
    M4.w = lrelu(dec_f(g_maxh[3]) + dec_f(g_maxh[7]));
    float4 hs = *(const float4*)(g_Hs + (size_t)node * 4);

    float4 acc0 = make_float4(0.f, 0.f, 0.f, 0.f);
    float4 acc1 = make_float4(0.f, 0.f, 0.f, 0.f);
    float4 acc2 = make_float4(0.f, 0.f, 0.f, 0.f);
    float4 acc3 = make_float4(0.f, 0.f, 0.f, 0.f);
    float4 dsum = make_float4(0.f, 0.f, 0.f, 0.f);

    for (int base = start; base < end; base += 32) {
        int cnt = min(32, end - base);
        int tgt = 0;
        float4 e4 = make_float4(0.f, 0.f, 0.f, 0.f);
        if (lane < cnt) {
            tgt = g_csr[base + lane];
            float4 ht = *(const float4*)(g_Ht + (size_t)tgt * 4);
            e4.x = __expf(lrelu(hs.x + ht.x) - M4.x);
            e4.y = __expf(lrelu(hs.y + ht.y) - M4.y);
            e4.z = __expf(lrelu(hs.z + ht.z) - M4.z);
            e4.w = __expf(lrelu(hs.w + ht.w) - M4.w);
            dsum.x += e4.x; dsum.y += e4.y; dsum.z += e4.z; dsum.w += e4.w;
        }
        s_tgt[wid][lane] = tgt;
        *(float4*)&s_e[wid][lane * 4] = e4;
        __syncwarp();
        if (cnt == 32) {
#pragma unroll
            for (int j = 0; j < 32; j += 4) {
                agg_step(j,     lane, h, s_tgt[wid], s_e[wid], acc0);
                agg_step(j + 1, lane, h, s_tgt[wid], s_e[wid], acc1);
                agg_step(j + 2, lane, h, s_tgt[wid], s_e[wid], acc2);
                agg_step(j + 3, lane, h, s_tgt[wid], s_e[wid], acc3);
            }
        } else {
#pragma unroll 4
            for (int j = 0; j < cnt; j++)
                agg_step(j, lane, h, s_tgt[wid], s_e[wid], acc0);
        }
        __syncwarp();
    }

    float4 acc = make_float4(acc0.x + acc1.x + acc2.x + acc3.x,
                             acc0.y + acc1.y + acc2.y + acc3.y,
                             acc0.z + acc1.z + acc2.z + acc3.z,
                             acc0.w + acc1.w + acc2.w + acc3.w);
#pragma unroll
    for (int o = 16; o > 0; o >>= 1) {
        dsum.x += __shfl_xor_sync(0xffffffffu, dsum.x, o);
        dsum.y += __shfl_xor_sync(0xffffffffu, dsum.y, o);
        dsum.z += __shfl_xor_sync(0xffffffffu, dsum.z, o);
        dsum.w += __shfl_xor_sync(0xffffffffu, dsum.w, o);
    }
    float dh = (h == 0) ? dsum.x : (h == 1) ? dsum.y : (h == 2) ? dsum.z : dsum.w;
    float sc = 1.0f / (dh + 1e-8f);
    acc.x *= sc; acc.y *= sc; acc.z *= sc; acc.w *= sc;
    acc.x = acc.x > 0.f ? acc.x : expm1f(acc.x);
    acc.y = acc.y > 0.f ? acc.y : expm1f(acc.y);
    acc.z = acc.z > 0.f ? acc.z : expm1f(acc.z);
    acc.w = acc.w > 0.f ? acc.w : expm1f(acc.w);
    *(float4*)(out + (size_t)node * DIM + lane * 4) = acc;

    if (lane == 0) g_cur[node] = 0;   // reset for next graph replay
}

extern "C" void kernel_launch(void* const* d_in, const int* in_sizes, int n_in,
                              void* d_out, int out_size) {
    const float* X  = (const float*)d_in[0];
    const int* EI   = (const int*)d_in[1];
    const float* W  = (const float*)d_in[2];
    const float* Al = (const float*)d_in[3];
    const float* Ar = (const float*)d_in[4];
    float* out = (float*)d_out;

    static cudaStream_t sA = nullptr, sB = nullptr;
    static cudaEvent_t evFork = nullptr, evA = nullptr, evB = nullptr;
    if (sA == nullptr) {
        cudaStreamCreateWithFlags(&sA, cudaStreamNonBlocking);
        cudaStreamCreateWithFlags(&sB, cudaStreamNonBlocking);
        cudaEventCreateWithFlags(&evFork, cudaEventDisableTiming);
        cudaEventCreateWithFlags(&evA, cudaEventDisableTiming);
        cudaEventCreateWithFlags(&evB, cudaEventDisableTiming);
    }

    cudaEventRecord(evFork, 0);
    cudaStreamWaitEvent(sA, evFork, 0);
    cudaStreamWaitEvent(sB, evFork, 0);

    // chain A: X->fp16, then fp16 HMMA GEMM + fused scores
    xcvt_kernel<<<(NN * DIM / 8 + 255) / 256, 256, 0, sA>>>(X);
    gemm_f16<<<(NN + 127) / 128, 256, 0, sA>>>(W, Al, Ar);
    cudaEventRecord(evA, sA);

    // chain B: single-pass bucket CSR
    scatter_kernel<<<(EE + 255) / 256, 256, 0, sB>>>(EI);
    cudaEventRecord(evB, sB);

    cudaStreamWaitEvent(0, evA, 0);
    cudaStreamWaitEvent(0, evB, 0);
    agg_kernel<<<(NN + WPB - 1) / WPB, WPB * 32>>>(out);
}

// round 17
// speedup vs baseline: 1.0803x; 1.0803x over previous
#include <cuda_runtime.h>
#include <cuda_fp16.h>
#include <math.h>

#define NN 50000
#define EE 1600000
#define DIM 128
#define HEADS 4
#define ODIM 32
#define ALPHA 0.2f
#define WPB 8
#define SCAN_B 512
#define NSCB ((NN + SCAN_B - 1) / SCAN_B)   // 98

// ---------------- device scratch ----------------
__device__ __align__(16) __half g_Xh[NN * DIM];   // fp16 copy of X
__device__ __align__(16) __half g_Hh[NN * DIM];   // fp16 features
__device__ __align__(16) float  g_Hs[NN * HEADS];
__device__ __align__(16) float  g_Ht[NN * HEADS];
__device__ int g_cnt[NN];        // zero at load; re-zeroed by scan3
__device__ int g_off[NN + 1];
__device__ int g_cur[NN];
__device__ int g_csr[EE];
__device__ int g_part[NSCB];
__device__ int g_partoff[NSCB];
__device__ unsigned g_maxh[8];

__device__ __forceinline__ unsigned enc_f(float f) {
    unsigned u = __float_as_uint(f);
    return (u & 0x80000000u) ? ~u : (u | 0x80000000u);
}
__device__ __forceinline__ float dec_f(unsigned u) {
    return (u & 0x80000000u) ? __uint_as_float(u ^ 0x80000000u)
                             : __uint_as_float(~u);
}
__device__ __forceinline__ float lrelu(float x) { return x > 0.f ? x : ALPHA * x; }

__device__ __forceinline__ void mma_f16(float* c, const unsigned* a,
                                        unsigned b0, unsigned b1) {
    asm volatile(
        "mma.sync.aligned.m16n8k16.row.col.f32.f16.f16.f32 "
        "{%0,%1,%2,%3}, {%4,%5,%6,%7}, {%8,%9}, {%0,%1,%2,%3};\n"
        : "+f"(c[0]), "+f"(c[1]), "+f"(c[2]), "+f"(c[3])
        : "r"(a[0]), "r"(a[1]), "r"(a[2]), "r"(a[3]), "r"(b0), "r"(b1));
}

// ---------------- chain A, K0: X -> fp16 ----------------
__global__ void xcvt_kernel(const float* __restrict__ X) {
    int i = blockIdx.x * blockDim.x + threadIdx.x;   // one per 8 elems
    if (i < NN * DIM / 8) {
        const float4* p = (const float4*)X + (size_t)i * 2;
        float4 v0 = p[0], v1 = p[1];
        __half2 h[4];
        h[0] = __floats2half2_rn(v0.x, v0.y);
        h[1] = __floats2half2_rn(v0.z, v0.w);
        h[2] = __floats2half2_rn(v1.x, v1.y);
        h[3] = __floats2half2_rn(v1.z, v1.w);
        *(uint4*)(g_Xh + (size_t)i * 8) = *(uint4*)h;
    }
}

// ---------------- chain A, K1: fp16 HMMA GEMM + fused scores/maxes ----------------
__global__ __launch_bounds__(256) void gemm_f16(const float* __restrict__ W,
                                                const float* __restrict__ Al,
                                                const float* __restrict__ Ar) {
    if (blockIdx.x == 0 && threadIdx.x < 8) g_maxh[threadIdx.x] = 0u;
    __shared__ __align__(16) __half Xs[128][72];
    __shared__ __align__(16) __half Wt[128][72];   // W transposed: [n][k]
    __shared__ unsigned sm8[8];
    const int tid  = threadIdx.x;
    const int lane = tid & 31;
    const int warp = tid >> 5;
    const int wr = warp >> 1;
    const int wc = warp & 1;
    const int g   = lane >> 2;
    const int tig = lane & 3;
    const int m0 = blockIdx.x * 128;
    if (tid < 8) sm8[tid] = 0u;

    float c[2][8][4];
#pragma unroll
    for (int mi = 0; mi < 2; mi++)
#pragma unroll
        for (int ni = 0; ni < 8; ni++)
#pragma unroll
            for (int j = 0; j < 4; j++) c[mi][ni][j] = 0.f;

    for (int kc = 0; kc < DIM; kc += 64) {
        __syncthreads();
        for (int idx = tid; idx < 128 * 8; idx += 256) {
            int row = idx >> 3;
            int c8  = (idx & 7) * 8;
            int gm = m0 + row;
            uint4 v = make_uint4(0u, 0u, 0u, 0u);
            if (gm < NN) v = *(const uint4*)(g_Xh + (size_t)gm * DIM + kc + c8);
            *(uint4*)&Xs[row][c8] = v;
        }
        for (int idx = tid; idx < 64 * 32; idx += 256) {
            int k  = idx >> 5;
            int n4 = (idx & 31) * 4;
            float4 w = *(const float4*)(W + (size_t)(kc + k) * DIM + n4);
            Wt[n4 + 0][k] = __float2half(w.x);
            Wt[n4 + 1][k] = __float2half(w.y);
            Wt[n4 + 2][k] = __float2half(w.z);
            Wt[n4 + 3][k] = __float2half(w.w);
        }
        __syncthreads();

#pragma unroll
        for (int ks = 0; ks < 4; ks++) {
            const int k0 = ks * 16;
            unsigned a[2][4];
#pragma unroll
            for (int mi = 0; mi < 2; mi++) {
                int r = wr * 32 + mi * 16;
                a[mi][0] = *(const unsigned*)&Xs[r + g][k0 + tig * 2];
                a[mi][1] = *(const unsigned*)&Xs[r + g + 8][k0 + tig * 2];
                a[mi][2] = *(const unsigned*)&Xs[r + g][k0 + tig * 2 + 8];
                a[mi][3] = *(const unsigned*)&Xs[r + g + 8][k0 + tig * 2 + 8];
            }
#pragma unroll
            for (int ni = 0; ni < 8; ni++) {
                int n = wc * 64 + ni * 8 + g;
                unsigned b0 = *(const unsigned*)&Wt[n][k0 + tig * 2];
                unsigned b1 = *(const unsigned*)&Wt[n][k0 + tig * 2 + 8];
                mma_f16(c[0][ni], a[0], b0, b1);
                mma_f16(c[1][ni], a[1], b0, b1);
            }
        }
    }

    const int head0 = wc * 2, head1 = wc * 2 + 1;
    float alv0[8], arv0[8], alv1[8], arv1[8];
#pragma unroll
    for (int ni = 0; ni < 4; ni++)
#pragma unroll
        for (int j = 0; j < 2; j++) {
            int o = ni * 8 + tig * 2 + j;
            alv0[ni * 2 + j] = Al[head0 * ODIM + o];
            arv0[ni * 2 + j] = Ar[head0 * ODIM + o];
            alv1[ni * 2 + j] = Al[head1 * ODIM + o];
            arv1[ni * 2 + j] = Ar[head1 * ODIM + o];
        }
    float mx_s0 = -1e30f, mx_t0 = -1e30f, mx_s1 = -1e30f, mx_t1 = -1e30f;
#pragma unroll
    for (int mi = 0; mi < 2; mi++)
#pragma unroll
        for (int half = 0; half < 2; half++) {
            int row = m0 + wr * 32 + mi * 16 + g + 8 * half;
            float s0 = 0.f, t0 = 0.f, s1 = 0.f, t1 = 0.f;
            if (row < NN) {
#pragma unroll
                for (int ni = 0; ni < 8; ni++) {
                    float v0 = c[mi][ni][half * 2];
                    float v1 = c[mi][ni][half * 2 + 1];
                    *(__half2*)(g_Hh + (size_t)row * DIM + wc * 64 + ni * 8 + tig * 2) =
                        __floats2half2_rn(v0, v1);
                    if (ni < 4) {
                        s0 = fmaf(v0, alv0[ni * 2], s0);
                        s0 = fmaf(v1, alv0[ni * 2 + 1], s0);
                        t0 = fmaf(v0, arv0[ni * 2], t0);
                        t0 = fmaf(v1, arv0[ni * 2 + 1], t0);
                    } else {
                        s1 = fmaf(v0, alv1[(ni - 4) * 2], s1);
                        s1 = fmaf(v1, alv1[(ni - 4) * 2 + 1], s1);
                        t1 = fmaf(v0, arv1[(ni - 4) * 2], t1);
                        t1 = fmaf(v1, arv1[(ni - 4) * 2 + 1], t1);
                    }
                }
            }
            s0 += __shfl_xor_sync(0xffffffffu, s0, 1);
            t0 += __shfl_xor_sync(0xffffffffu, t0, 1);
            s1 += __shfl_xor_sync(0xffffffffu, s1, 1);
            t1 += __shfl_xor_sync(0xffffffffu, t1, 1);
            s0 += __shfl_xor_sync(0xffffffffu, s0, 2);
            t0 += __shfl_xor_sync(0xffffffffu, t0, 2);
            s1 += __shfl_xor_sync(0xffffffffu, s1, 2);
            t1 += __shfl_xor_sync(0xffffffffu, t1, 2);
            if (tig == 0 && row < NN) {
                g_Hs[(size_t)row * 4 + head0] = s0;
                g_Ht[(size_t)row * 4 + head0] = t0;
                g_Hs[(size_t)row * 4 + head1] = s1;
                g_Ht[(size_t)row * 4 + head1] = t1;
                mx_s0 = fmaxf(mx_s0, s0);
                mx_t0 = fmaxf(mx_t0, t0);
                mx_s1 = fmaxf(mx_s1, s1);
                mx_t1 = fmaxf(mx_t1, t1);
            }
        }
    if (tig == 0) {
        atomicMax(&sm8[head0],     enc_f(mx_s0));
        atomicMax(&sm8[4 + head0], enc_f(mx_t0));
        atomicMax(&sm8[head1],     enc_f(mx_s1));
        atomicMax(&sm8[4 + head1], enc_f(mx_t1));
    }
    __syncthreads();
    if (tid < 8) atomicMax(&g_maxh[tid], sm8[tid]);
}

// ---------------- chain B, K3: histogram ----------------
__global__ void hist_kernel(const int* __restrict__ ei) {
    int e = blockIdx.x * blockDim.x + threadIdx.x;
    if (e < EE) atomicAdd(&g_cnt[ei[e]], 1);
}

// ---------------- chain B, K4a: block partial sums ----------------
__global__ __launch_bounds__(SCAN_B) void scan1_kernel() {
    __shared__ int sw[SCAN_B / 32];
    int i = blockIdx.x * SCAN_B + threadIdx.x;
    int v = (i < NN) ? g_cnt[i] : 0;
#pragma unroll
    for (int o = 16; o > 0; o >>= 1) v += __shfl_xor_sync(0xffffffffu, v, o);
    int lane = threadIdx.x & 31, wid = threadIdx.x >> 5;
    if (lane == 0) sw[wid] = v;
    __syncthreads();
    if (wid == 0) {
        v = (lane < SCAN_B / 32) ? sw[lane] : 0;
#pragma unroll
        for (int o = 8; o > 0; o >>= 1) v += __shfl_xor_sync(0xffffffffu, v, o);
        if (lane == 0) g_part[blockIdx.x] = v;
    }
}

// ---------------- chain B, K4b: scan the 98 partials ----------------
__global__ __launch_bounds__(128) void scan2_kernel() {
    __shared__ int s[128];
    int t = threadIdx.x;
    s[t] = (t < NSCB) ? g_part[t] : 0;
    __syncthreads();
#pragma unroll
    for (int off = 1; off < 128; off <<= 1) {
        int v = (t >= off) ? s[t - off] : 0;
        __syncthreads();
        s[t] += v;
        __syncthreads();
    }
    if (t < NSCB) g_partoff[t] = (t == 0) ? 0 : s[t - 1];
}

// ---------------- chain B, K4c: in-block exclusive scan + write offsets ----------------
__global__ __launch_bounds__(SCAN_B) void scan3_kernel() {
    __shared__ int s[SCAN_B];
    int t = threadIdx.x;
    int i = blockIdx.x * SCAN_B + t;
    int v = (i < NN) ? g_cnt[i] : 0;
    s[t] = v;
    __syncthreads();
#pragma unroll
    for (int off = 1; off < SCAN_B; off <<= 1) {
        int u = (t >= off) ? s[t - off] : 0;
        __syncthreads();
        s[t] += u;
        __syncthreads();
    }
    if (i < NN) {
        int prefix = g_partoff[blockIdx.x] + s[t] - v;
        g_off[i] = prefix;
        g_cur[i] = prefix;
        g_cnt[i] = 0;
        if (i == NN - 1) g_off[NN] = EE;
    }
}

// ---------------- chain B, K5: scatter edges into CSR ----------------
__global__ void scatter_kernel(const int* __restrict__ ei) {
    int e = blockIdx.x * blockDim.x + threadIdx.x;
    if (e < EE) {
        int src = ei[e];
        int tgt = ei[EE + e];
        int p = atomicAdd(&g_cur[src], 1);
        g_csr[p] = tgt;
    }
}

// ---------------- join, K6: fused softmax + aggregation + ELU ----------------
__device__ __forceinline__ void agg_step(int j, int lane, int h,
                                         const int* s_tgt, const float* s_e,
                                         float4& acc) {
    int t = s_tgt[j];
    float ej = s_e[j * 4 + h];
    const __half2* hp = (const __half2*)(g_Hh + (size_t)t * DIM + lane * 4);
    __half2 a = hp[0], b = hp[1];
    float2 fa = __half22float2(a);
    float2 fb = __half22float2(b);
    acc.x = fmaf(ej, fa.x, acc.x);
    acc.y = fmaf(ej, fa.y, acc.y);
    acc.z = fmaf(ej, fb.x, acc.z);
    acc.w = fmaf(ej, fb.y, acc.w);
}

// __launch_bounds__(256, 5): force <=51 regs -> 5 blocks/SM (62.5% occ ceiling).
// Profile showed 58 regs -> 40% occ, issue 43.5%, L2 only 22.6% (latency-bound).
__global__ __launch_bounds__(WPB * 32, 5) void agg_kernel(float* __restrict__ out) {
    __shared__ int   s_tgt[WPB][32];
    __shared__ float s_e[WPB][32 * 4];
    int wid  = threadIdx.x >> 5;
    int lane = threadIdx.x & 31;
    int node = blockIdx.x * WPB + wid;
    if (node >= NN) return;
    int h = lane >> 3;
    int start = g_off[node];
    int end   = g_off[node + 1];
    float4 M4;
    M4.x = lrelu(dec_f(g_maxh[0]) + dec_f(g_maxh[4]));
    M4.y = lrelu(dec_f(g_maxh[1]) + dec_f(g_maxh[5]));
    M4.z = lrelu(dec_f(g_maxh[2]) + dec_f(g_maxh[6]));
    M4.w = lrelu(dec_f(g_maxh[3]) + dec_f(g_maxh[7]));
    float4 hs = *(const float4*)(g_Hs + (size_t)node * 4);

    float4 acc0 = make_float4(0.f, 0.f, 0.f, 0.f);
    float4 acc1 = make_float4(0.f, 0.f, 0.f, 0.f);
    float4 acc2 = make_float4(0.f, 0.f, 0.f, 0.f);
    float4 acc3 = make_float4(0.f, 0.f, 0.f, 0.f);
    float4 dsum = make_float4(0.f, 0.f, 0.f, 0.f);

    for (int base = start; base < end; base += 32) {
        int cnt = min(32, end - base);
        int tgt = 0;
        float4 e4 = make_float4(0.f, 0.f, 0.f, 0.f);
        if (lane < cnt) {
            tgt = g_csr[base + lane];
            float4 ht = *(const float4*)(g_Ht + (size_t)tgt * 4);
            e4.x = __expf(lrelu(hs.x + ht.x) - M4.x);
            e4.y = __expf(lrelu(hs.y + ht.y) - M4.y);
            e4.z = __expf(lrelu(hs.z + ht.z) - M4.z);
            e4.w = __expf(lrelu(hs.w + ht.w) - M4.w);
            dsum.x += e4.x; dsum.y += e4.y; dsum.z += e4.z; dsum.w += e4.w;
        }
        s_tgt[wid][lane] = tgt;
        *(float4*)&s_e[wid][lane * 4] = e4;
        __syncwarp();
        if (cnt == 32) {
#pragma unroll
            for (int j = 0; j < 32; j += 4) {
                agg_step(j,     lane, h, s_tgt[wid], s_e[wid], acc0);
                agg_step(j + 1, lane, h, s_tgt[wid], s_e[wid], acc1);
                agg_step(j + 2, lane, h, s_tgt[wid], s_e[wid], acc2);
                agg_step(j + 3, lane, h, s_tgt[wid], s_e[wid], acc3);
            }
        } else {
#pragma unroll 4
            for (int j = 0; j < cnt; j++)
                agg_step(j, lane, h, s_tgt[wid], s_e[wid], acc0);
        }
        __syncwarp();
    }

    float4 acc = make_float4(acc0.x + acc1.x + acc2.x + acc3.x,
                             acc0.y + acc1.y + acc2.y + acc3.y,
                             acc0.z + acc1.z + acc2.z + acc3.z,
                             acc0.w + acc1.w + acc2.w + acc3.w);
#pragma unroll
    for (int o = 16; o > 0; o >>= 1) {
        dsum.x += __shfl_xor_sync(0xffffffffu, dsum.x, o);
        dsum.y += __shfl_xor_sync(0xffffffffu, dsum.y, o);
        dsum.z += __shfl_xor_sync(0xffffffffu, dsum.z, o);
        dsum.w += __shfl_xor_sync(0xffffffffu, dsum.w, o);
    }
    float dh = (h == 0) ? dsum.x : (h == 1) ? dsum.y : (h == 2) ? dsum.z : dsum.w;
    float sc = 1.0f / (dh + 1e-8f);
    acc.x *= sc; acc.y *= sc; acc.z *= sc; acc.w *= sc;
    acc.x = acc.x > 0.f ? acc.x : expm1f(acc.x);
    acc.y = acc.y > 0.f ? acc.y : expm1f(acc.y);
    acc.z = acc.z > 0.f ? acc.z : expm1f(acc.z);
    acc.w = acc.w > 0.f ? acc.w : expm1f(acc.w);
    *(float4*)(out + (size_t)node * DIM + lane * 4) = acc;
}

extern "C" void kernel_launch(void* const* d_in, const int* in_sizes, int n_in,
                              void* d_out, int out_size) {
    const float* X  = (const float*)d_in[0];
    const int* EI   = (const int*)d_in[1];
    const float* W  = (const float*)d_in[2];
    const float* Al = (const float*)d_in[3];
    const float* Ar = (const float*)d_in[4];
    float* out = (float*)d_out;

    static cudaStream_t sA = nullptr, sB = nullptr;
    static cudaEvent_t evFork = nullptr, evA = nullptr, evB = nullptr;
    if (sA == nullptr) {
        cudaStreamCreateWithFlags(&sA, cudaStreamNonBlocking);
        cudaStreamCreateWithFlags(&sB, cudaStreamNonBlocking);
        cudaEventCreateWithFlags(&evFork, cudaEventDisableTiming);
        cudaEventCreateWithFlags(&evA, cudaEventDisableTiming);
        cudaEventCreateWithFlags(&evB, cudaEventDisableTiming);
    }

    cudaEventRecord(evFork, 0);
    cudaStreamWaitEvent(sA, evFork, 0);
    cudaStreamWaitEvent(sB, evFork, 0);

    // chain A: X->fp16, then fp16 HMMA GEMM + fused scores
    xcvt_kernel<<<(NN * DIM / 8 + 255) / 256, 256, 0, sA>>>(X);
    gemm_f16<<<(NN + 127) / 128, 256, 0, sA>>>(W, Al, Ar);
    cudaEventRecord(evA, sA);

    // chain B: CSR build
    hist_kernel<<<(EE + 255) / 256, 256, 0, sB>>>(EI);
    scan1_kernel<<<NSCB, SCAN_B, 0, sB>>>();
    scan2_kernel<<<1, 128, 0, sB>>>();
    scan3_kernel<<<NSCB, SCAN_B, 0, sB>>>();
    scatter_kernel<<<(EE + 255) / 256, 256, 0, sB>>>(EI);
    cudaEventRecord(evB, sB);

    cudaStreamWaitEvent(0, evA, 0);
    cudaStreamWaitEvent(0, evB, 0);
    agg_kernel<<<(NN + WPB - 1) / WPB, WPB * 32>>>(out);
}